// round 7
// baseline (speedup 1.0000x reference)
#include <cuda_runtime.h>
#include <cuda_bf16.h>

#define FULL_MASK 0xffffffffu
#define EPW 128          // edges per warp-chunk (4 groups x 32 edges)
#define D   32           // feature dim (fixed by problem shape)
#define SPB 256          // segments per k_pre block

// Per-segment 1/max(count,1). Fully rewritten for all n<N on every call ->
// deterministic across graph replays; no allocation, no reset needed.
__device__ float g_inv[1 << 20];   // 4 MB, supports N up to 1M

// ---------------------------------------------------------------------------
// Kernel 1: counts via binary search on sorted sid + zero-init output rows.
// ---------------------------------------------------------------------------
__global__ void __launch_bounds__(SPB)
k_pre(const int* __restrict__ sid,
      float4*    __restrict__ out4,
      int E, int N)
{
    __shared__ int bnd[SPB + 1];

    const int tid      = threadIdx.x;
    const int seg_base = blockIdx.x * SPB;

    if (tid == 0 || tid == 1) {
        int target = seg_base + tid * SPB;
        int lo = 0, hi = E;
        while (lo < hi) {
            int mid = (lo + hi) >> 1;
            if (__ldg(sid + mid) < target) lo = mid + 1; else hi = mid;
        }
        bnd[tid * SPB] = lo;
    }
    __syncthreads();

    if (tid >= 1 && tid < SPB) {
        int target = seg_base + tid;
        int lo = bnd[0], hi = bnd[SPB];
        while (lo < hi) {
            int mid = (lo + hi) >> 1;
            if (__ldg(sid + mid) < target) lo = mid + 1; else hi = mid;
        }
        bnd[tid] = lo;
    }
    __syncthreads();

    const int seg = seg_base + tid;
    if (seg < N) {
        int cnt = bnd[tid + 1] - bnd[tid];
        g_inv[seg] = 1.0f / (float)max(cnt, 1);
    }

    // zero this block's 256 output rows (2048 quads), coalesced
    const long long qbase = (long long)seg_base * 8;
    const long long qend  = min(qbase + SPB * 8, (long long)N * 8);
    for (long long q = qbase + tid; q < qend; q += SPB)
        out4[q] = make_float4(0.f, 0.f, 0.f, 0.f);
}

// ---------------------------------------------------------------------------
// 128-bit reduction (fire-and-forget) — sm_90+ vector atomic
// ---------------------------------------------------------------------------
__device__ __forceinline__ void red_add_v4(float4* p, float4 s) {
    asm volatile("red.global.add.v4.f32 [%0], {%1, %2, %3, %4};"
                 :: "l"(p), "f"(s.x), "f"(s.y), "f"(s.z), "f"(s.w)
                 : "memory");
}

// flush: scale pre-fetched inv, REDG into out. No loads on this path.
__device__ __forceinline__ void flush_seg(float4* __restrict__ out4,
                                          int seg, float4 s, float inv, int sub) {
    red_add_v4(&out4[(long long)seg * 8 + sub],
               make_float4(s.x * inv, s.y * inv, s.z * inv, s.w * inv));
}

// ---------------------------------------------------------------------------
// Kernel 2: gather + sorted-segment mean.
// Warp = 4 groups of 8 lanes; group g owns contiguous edges
// [start + g*32, start + g*32 + 32). Lane sub owns feature columns
// [sub*4, sub*4+4) as a float4. Phase 1 issues 8 independent LDG.128 row
// reads (MLP=8/lane); phase 2 run-length accumulates. The segment's inv
// factor is PREFETCHED at run start so its L2 latency hides behind the
// subsequent gather loads; the flush is a pure FMUL + REDG.128.
// ---------------------------------------------------------------------------
__global__ void __launch_bounds__(256)
k_agg(const float* __restrict__ src,
      const int*   __restrict__ gidx,
      const int*   __restrict__ sid,
      float4*      __restrict__ out4,
      int E)
{
    const int lane = threadIdx.x & 31;
    const int sub  = lane & 7;
    const long long warp  = ((long long)blockIdx.x * blockDim.x + threadIdx.x) >> 5;
    const long long start = warp * (long long)EPW;
    if (start >= E) return;

    if (start + EPW <= E) {
        // ---------- fast path: full 128-edge chunk ----------
        int4 gi4 = __ldg((const int4*)(gidx + start) + lane);
        int4 si4 = __ldg((const int4*)(sid  + start) + lane);
        int gi[4] = {gi4.x, gi4.y, gi4.z, gi4.w};
        int si[4] = {si4.x, si4.y, si4.z, si4.w};

        int    cur = -1;
        float  curinv = 0.0f;
        float4 sum = make_float4(0.f, 0.f, 0.f, 0.f);
        int    cnt = 0;

        // prefetch inv for the first segment of this chunk (seg of edge 0)
        {
            int seg0 = __shfl_sync(FULL_MASK, si[0], 0, 8);
            curinv = __ldg(g_inv + seg0);
        }

        #pragma unroll
        for (int jo = 0; jo < 32; jo += 8) {
            float4 val[8];
            #pragma unroll
            for (int jj = 0; jj < 8; ++jj) {
                const int j = jo + jj;
                int idx = __shfl_sync(FULL_MASK, gi[j & 3], j >> 2, 8);
                val[jj] = __ldg((const float4*)(src + (long long)idx * D) + sub);
            }
            #pragma unroll
            for (int jj = 0; jj < 8; ++jj) {
                const int j = jo + jj;
                int seg = __shfl_sync(FULL_MASK, si[j & 3], j >> 2, 8);
                if (seg != cur) {
                    if (cnt) flush_seg(out4, cur, sum, curinv, sub);
                    if (cur >= 0) curinv = __ldg(g_inv + seg);  // prefetch new run
                    cur = seg; sum = make_float4(0.f, 0.f, 0.f, 0.f); cnt = 0;
                }
                sum.x += val[jj].x; sum.y += val[jj].y;
                sum.z += val[jj].z; sum.w += val[jj].w;
                ++cnt;
            }
        }
        if (cnt) flush_seg(out4, cur, sum, curinv, sub);
    } else {
        // ---------- tail path: partial chunk, per-group scalar loop ----------
        const int group = lane >> 3;
        long long gstart = start + (long long)group * 32;
        long long gend   = min(gstart + 32, (long long)E);

        int    cur = -1;
        float  curinv = 0.0f;
        float4 sum = make_float4(0.f, 0.f, 0.f, 0.f);
        int    cnt = 0;

        for (long long e = gstart; e < gend; ++e) {
            int idx = __ldg(gidx + e);
            int seg = __ldg(sid  + e);
            float4 v = __ldg((const float4*)(src + (long long)idx * D) + sub);
            if (seg != cur) {
                if (cnt) flush_seg(out4, cur, sum, curinv, sub);
                curinv = __ldg(g_inv + seg);
                cur = seg; sum = make_float4(0.f, 0.f, 0.f, 0.f); cnt = 0;
            }
            sum.x += v.x; sum.y += v.y; sum.z += v.z; sum.w += v.w;
            ++cnt;
        }
        if (cnt) flush_seg(out4, cur, sum, curinv, sub);
    }
}

// ---------------------------------------------------------------------------
extern "C" void kernel_launch(void* const* d_in, const int* in_sizes, int n_in,
                              void* d_out, int out_size)
{
    const float* src  = (const float*)d_in[0];   // [N, 32] f32
    const int*   gidx = (const int*)  d_in[1];   // [E] i32
    const int*   sid  = (const int*)  d_in[2];   // [E] i32 (sorted)
    float4*      out4 = (float4*)d_out;          // [N, 32] f32

    const int E = in_sizes[1];
    const int N = out_size / D;

    // 1) counts -> g_inv, zero output
    {
        int blocks = (N + SPB - 1) / SPB;
        k_pre<<<blocks, SPB>>>(sid, out4, E, N);
    }
    // 2) gather + pre-divided segment sum into out
    {
        long long warps  = ((long long)E + EPW - 1) / EPW;
        long long tcount = warps * 32;
        int threads = 256;
        int blocks  = (int)((tcount + threads - 1) / threads);
        k_agg<<<blocks, threads>>>(src, gidx, sid, out4, E);
    }
}

// round 8
// speedup vs baseline: 1.1875x; 1.1875x over previous
#include <cuda_runtime.h>
#include <cuda_bf16.h>

#define FULL_MASK 0xffffffffu
#define EPW 128          // edges per warp-chunk (4 groups x 32 edges)
#define D   32           // feature dim (fixed by problem shape)
#define SPB 256          // segments per k_pre block

// Per-segment 1/max(count,1). Fully rewritten for all n<N on every call ->
// deterministic across graph replays; no allocation, no reset needed.
__device__ float g_inv[1 << 20];   // 4 MB, supports N up to 1M

// ---------------------------------------------------------------------------
// Kernel 1: counts via binary search on sorted sid -> g_inv, zero out.
// ---------------------------------------------------------------------------
__global__ void __launch_bounds__(SPB)
k_pre(const int* __restrict__ sid,
      float4*    __restrict__ out4,
      int E, int N)
{
    __shared__ int bnd[SPB + 1];

    const int tid      = threadIdx.x;
    const int seg_base = blockIdx.x * SPB;

    if (tid == 0 || tid == 1) {
        int target = seg_base + tid * SPB;
        int lo = 0, hi = E;
        while (lo < hi) {
            int mid = (lo + hi) >> 1;
            if (__ldg(sid + mid) < target) lo = mid + 1; else hi = mid;
        }
        bnd[tid * SPB] = lo;
    }
    __syncthreads();

    if (tid >= 1 && tid < SPB) {
        int target = seg_base + tid;
        int lo = bnd[0], hi = bnd[SPB];
        while (lo < hi) {
            int mid = (lo + hi) >> 1;
            if (__ldg(sid + mid) < target) lo = mid + 1; else hi = mid;
        }
        bnd[tid] = lo;
    }
    __syncthreads();

    const int seg = seg_base + tid;
    if (seg < N) {
        int cnt = bnd[tid + 1] - bnd[tid];
        g_inv[seg] = 1.0f / (float)max(cnt, 1);
    }

    // zero this block's 256 output rows (2048 quads), coalesced
    const long long qbase = (long long)seg_base * 8;
    const long long qend  = min(qbase + SPB * 8, (long long)N * 8);
    for (long long q = qbase + tid; q < qend; q += SPB)
        out4[q] = make_float4(0.f, 0.f, 0.f, 0.f);
}

// ---------------------------------------------------------------------------
// Flush: raw sums, fire-and-forget scalar atomics (round-3 proven path).
// ---------------------------------------------------------------------------
__device__ __forceinline__ void flush_seg(float* __restrict__ out, int seg,
                                          float4 s, int sub) {
    float* p = out + (long long)seg * D + sub * 4;
    atomicAdd(p + 0, s.x);
    atomicAdd(p + 1, s.y);
    atomicAdd(p + 2, s.z);
    atomicAdd(p + 3, s.w);
}

// ---------------------------------------------------------------------------
// Kernel 2: gather + sorted-segment sum (round-3 engine, verbatim).
// Warp = 4 groups of 8 lanes. Group g owns contiguous edges
// [start + g*32, start + g*32 + 32). Lane sub owns feature columns
// [sub*4, sub*4+4) as a float4. Phase 1 issues 8 independent LDG.128 row
// reads (MLP=8/lane); phase 2 run-length accumulates, flushing raw sums
// with scalar REDGs on segment change. NOTHING else in the inner loop.
// ---------------------------------------------------------------------------
__global__ void __launch_bounds__(256)
k_agg(const float* __restrict__ src,
      const int*   __restrict__ gidx,
      const int*   __restrict__ sid,
      float*       __restrict__ out,
      int E)
{
    const int lane = threadIdx.x & 31;
    const int sub  = lane & 7;
    const long long warp  = ((long long)blockIdx.x * blockDim.x + threadIdx.x) >> 5;
    const long long start = warp * (long long)EPW;
    if (start >= E) return;

    if (start + EPW <= E) {
        // ---------- fast path: full 128-edge chunk ----------
        int4 gi4 = __ldg((const int4*)(gidx + start) + lane);
        int4 si4 = __ldg((const int4*)(sid  + start) + lane);
        int gi[4] = {gi4.x, gi4.y, gi4.z, gi4.w};
        int si[4] = {si4.x, si4.y, si4.z, si4.w};

        int    cur = -1;
        float4 sum = make_float4(0.f, 0.f, 0.f, 0.f);

        #pragma unroll
        for (int jo = 0; jo < 32; jo += 8) {
            float4 val[8];
            #pragma unroll
            for (int jj = 0; jj < 8; ++jj) {
                const int j = jo + jj;
                int idx = __shfl_sync(FULL_MASK, gi[j & 3], j >> 2, 8);
                val[jj] = __ldg((const float4*)(src + (long long)idx * D) + sub);
            }
            #pragma unroll
            for (int jj = 0; jj < 8; ++jj) {
                const int j = jo + jj;
                int seg = __shfl_sync(FULL_MASK, si[j & 3], j >> 2, 8);
                if (seg != cur) {
                    if (cur >= 0) flush_seg(out, cur, sum, sub);
                    cur = seg; sum = make_float4(0.f, 0.f, 0.f, 0.f);
                }
                sum.x += val[jj].x; sum.y += val[jj].y;
                sum.z += val[jj].z; sum.w += val[jj].w;
            }
        }
        flush_seg(out, cur, sum, sub);
    } else {
        // ---------- tail path: partial chunk, per-group scalar loop ----------
        const int group = lane >> 3;
        long long gstart = start + (long long)group * 32;
        long long gend   = min(gstart + 32, (long long)E);

        int    cur = -1;
        float4 sum = make_float4(0.f, 0.f, 0.f, 0.f);

        for (long long e = gstart; e < gend; ++e) {
            int idx = __ldg(gidx + e);
            int seg = __ldg(sid  + e);
            float4 v = __ldg((const float4*)(src + (long long)idx * D) + sub);
            if (seg != cur) {
                if (cur >= 0) flush_seg(out, cur, sum, sub);
                cur = seg; sum = make_float4(0.f, 0.f, 0.f, 0.f);
            }
            sum.x += v.x; sum.y += v.y; sum.z += v.z; sum.w += v.w;
        }
        if (cur >= 0) flush_seg(out, cur, sum, sub);
    }
}

// ---------------------------------------------------------------------------
// Kernel 3: out[n][:] *= g_inv[n]   (pure streaming, 26 MB)
// ---------------------------------------------------------------------------
__global__ void k_fin(float4* __restrict__ out4, int nq) {
    int i = blockIdx.x * blockDim.x + threadIdx.x;
    if (i >= nq) return;
    float4 v = out4[i];
    float  inv = __ldg(g_inv + (i >> 3));   // 8 threads same addr -> broadcast
    v.x *= inv; v.y *= inv; v.z *= inv; v.w *= inv;
    out4[i] = v;
}

// ---------------------------------------------------------------------------
extern "C" void kernel_launch(void* const* d_in, const int* in_sizes, int n_in,
                              void* d_out, int out_size)
{
    const float* src  = (const float*)d_in[0];   // [N, 32] f32
    const int*   gidx = (const int*)  d_in[1];   // [E] i32
    const int*   sid  = (const int*)  d_in[2];   // [E] i32 (sorted)
    float*       out  = (float*)d_out;           // [N, 32] f32

    const int E = in_sizes[1];
    const int N = out_size / D;

    // 1) counts -> g_inv, zero output
    {
        int blocks = (N + SPB - 1) / SPB;
        k_pre<<<blocks, SPB>>>(sid, (float4*)out, E, N);
    }
    // 2) gather + raw segment sums into out (atomics)
    {
        long long warps  = ((long long)E + EPW - 1) / EPW;
        long long tcount = warps * 32;
        int threads = 256;
        int blocks  = (int)((tcount + threads - 1) / threads);
        k_agg<<<blocks, threads>>>(src, gidx, sid, out, E);
    }
    // 3) scale by 1/count
    {
        int nq      = out_size / 4;
        int threads = 256;
        int blocks  = (nq + threads - 1) / threads;
        k_fin<<<blocks, threads>>>((float4*)out, nq);
    }
}

// round 9
// speedup vs baseline: 1.3002x; 1.0949x over previous
#include <cuda_runtime.h>
#include <cuda_bf16.h>

#define FULL_MASK 0xffffffffu
#define EPW 128          // edges per warp-chunk (4 groups x 32 edges)
#define D   32           // feature dim (fixed by problem shape)

// Segment start offsets: g_start[n] = lower_bound(sid, n), g_start[N] = E.
// Every entry [0..N] is rewritten on every call -> deterministic across
// graph replays; no allocation, no reset needed.
__device__ int g_start[(1 << 20) + 1];   // supports N up to 1M

// ---------------------------------------------------------------------------
// Kernel 1: linear boundary scan over sorted sid -> g_start, and zero out.
// Thread i owns edges [4i, 4i+4): one int4 load + one scalar peek at the
// next element. A boundary sid[e] != sid[e+1] means segment s starts at e+1
// for every s in (sid[e], sid[e+1]] (covers empty segments). Thread 0 also
// writes starts for s in [0, sid[0]]; the thread holding edge E-1 writes
// starts for s in (sid[E-1], N]. Fully parallel, no dependent load chains.
// Each thread also zeroes one output quad (independent latency-filling work).
// ---------------------------------------------------------------------------
__global__ void __launch_bounds__(256)
k_scan(const int* __restrict__ sid,
       float4*    __restrict__ out4,
       int E, int N, int nq)
{
    const int i = blockIdx.x * blockDim.x + threadIdx.x;

    // zero output (nq <= number of threads by construction)
    if (i < nq) out4[i] = make_float4(0.f, 0.f, 0.f, 0.f);

    const int e0 = i * 4;
    if (e0 >= E) return;

    int s0, s1, s2, s3;
    if (e0 + 4 <= E) {
        int4 v = __ldg((const int4*)(sid) + i);
        s0 = v.x; s1 = v.y; s2 = v.z; s3 = v.w;
    } else {
        s0 = __ldg(sid + e0);
        s1 = (e0 + 1 < E) ? __ldg(sid + e0 + 1) : s0;
        s2 = (e0 + 2 < E) ? __ldg(sid + e0 + 2) : s1;
        s3 = (e0 + 3 < E) ? __ldg(sid + e0 + 3) : s2;
    }
    // next element after this thread's span (sentinel N past the end)
    const int e_last = min(e0 + 3, E - 1);
    const int nxt = (e0 + 4 < E) ? __ldg(sid + e0 + 4)
                                 : ((e0 + 4 == E) ? N : N);

    // head: starts for s in [0, sid[0]]
    if (i == 0)
        for (int s = 0; s <= s0; ++s) g_start[s] = 0;

    // boundaries inside the span
    int a[5] = {s0, s1, s2, s3, nxt};
    #pragma unroll
    for (int j = 0; j < 4; ++j) {
        const int e = e0 + j;
        if (e < E && e + 1 <= E) {
            const int cs = a[j];
            const int ns = (e == e_last) ? ((e + 1 == E) ? N : a[j + 1])
                                         : a[j + 1];
            if (e + 1 == E) {
                // tail: starts for s in (sid[E-1], N]
                for (int s = cs + 1; s <= N; ++s) g_start[s] = E;
            } else if (ns != cs) {
                for (int s = cs + 1; s <= ns; ++s) g_start[s] = e + 1;
            }
        }
    }
}

// ---------------------------------------------------------------------------
// Flush: raw sums, fire-and-forget scalar atomics (proven round-3/8 path).
// ---------------------------------------------------------------------------
__device__ __forceinline__ void flush_seg(float* __restrict__ out, int seg,
                                          float4 s, int sub) {
    float* p = out + (long long)seg * D + sub * 4;
    atomicAdd(p + 0, s.x);
    atomicAdd(p + 1, s.y);
    atomicAdd(p + 2, s.z);
    atomicAdd(p + 3, s.w);
}

// ---------------------------------------------------------------------------
// Kernel 2: gather + sorted-segment sum (round-3 engine, verbatim).
// ---------------------------------------------------------------------------
__global__ void __launch_bounds__(256)
k_agg(const float* __restrict__ src,
      const int*   __restrict__ gidx,
      const int*   __restrict__ sid,
      float*       __restrict__ out,
      int E)
{
    const int lane = threadIdx.x & 31;
    const int sub  = lane & 7;
    const long long warp  = ((long long)blockIdx.x * blockDim.x + threadIdx.x) >> 5;
    const long long start = warp * (long long)EPW;
    if (start >= E) return;

    if (start + EPW <= E) {
        // ---------- fast path: full 128-edge chunk ----------
        int4 gi4 = __ldg((const int4*)(gidx + start) + lane);
        int4 si4 = __ldg((const int4*)(sid  + start) + lane);
        int gi[4] = {gi4.x, gi4.y, gi4.z, gi4.w};
        int si[4] = {si4.x, si4.y, si4.z, si4.w};

        int    cur = -1;
        float4 sum = make_float4(0.f, 0.f, 0.f, 0.f);

        #pragma unroll
        for (int jo = 0; jo < 32; jo += 8) {
            float4 val[8];
            #pragma unroll
            for (int jj = 0; jj < 8; ++jj) {
                const int j = jo + jj;
                int idx = __shfl_sync(FULL_MASK, gi[j & 3], j >> 2, 8);
                val[jj] = __ldg((const float4*)(src + (long long)idx * D) + sub);
            }
            #pragma unroll
            for (int jj = 0; jj < 8; ++jj) {
                const int j = jo + jj;
                int seg = __shfl_sync(FULL_MASK, si[j & 3], j >> 2, 8);
                if (seg != cur) {
                    if (cur >= 0) flush_seg(out, cur, sum, sub);
                    cur = seg; sum = make_float4(0.f, 0.f, 0.f, 0.f);
                }
                sum.x += val[jj].x; sum.y += val[jj].y;
                sum.z += val[jj].z; sum.w += val[jj].w;
            }
        }
        flush_seg(out, cur, sum, sub);
    } else {
        // ---------- tail path: partial chunk, per-group scalar loop ----------
        const int group = lane >> 3;
        long long gstart = start + (long long)group * 32;
        long long gend   = min(gstart + 32, (long long)E);

        int    cur = -1;
        float4 sum = make_float4(0.f, 0.f, 0.f, 0.f);

        for (long long e = gstart; e < gend; ++e) {
            int idx = __ldg(gidx + e);
            int seg = __ldg(sid  + e);
            float4 v = __ldg((const float4*)(src + (long long)idx * D) + sub);
            if (seg != cur) {
                if (cur >= 0) flush_seg(out, cur, sum, sub);
                cur = seg; sum = make_float4(0.f, 0.f, 0.f, 0.f);
            }
            sum.x += v.x; sum.y += v.y; sum.z += v.z; sum.w += v.w;
        }
        if (cur >= 0) flush_seg(out, cur, sum, sub);
    }
}

// ---------------------------------------------------------------------------
// Kernel 3: out[n][:] *= 1/max(count,1), count from g_start (cached loads).
// ---------------------------------------------------------------------------
__global__ void k_fin(float4* __restrict__ out4, int nq) {
    int i = blockIdx.x * blockDim.x + threadIdx.x;
    if (i >= nq) return;
    const int n  = i >> 3;
    const int a  = __ldg(g_start + n);
    const int b  = __ldg(g_start + n + 1);
    const float inv = 1.0f / (float)max(b - a, 1);
    float4 v = out4[i];
    v.x *= inv; v.y *= inv; v.z *= inv; v.w *= inv;
    out4[i] = v;
}

// ---------------------------------------------------------------------------
extern "C" void kernel_launch(void* const* d_in, const int* in_sizes, int n_in,
                              void* d_out, int out_size)
{
    const float* src  = (const float*)d_in[0];   // [N, 32] f32
    const int*   gidx = (const int*)  d_in[1];   // [E] i32
    const int*   sid  = (const int*)  d_in[2];   // [E] i32 (sorted)
    float*       out  = (float*)d_out;           // [N, 32] f32

    const int E  = in_sizes[1];
    const int N  = out_size / D;
    const int nq = out_size / 4;

    // 1) boundary scan -> g_start, zero out
    {
        int threads_needed = (E + 3) / 4;
        if (threads_needed < nq) threads_needed = nq;
        int blocks = (threads_needed + 255) / 256;
        k_scan<<<blocks, 256>>>(sid, (float4*)out, E, N, nq);
    }
    // 2) gather + raw segment sums into out (atomics)
    {
        long long warps  = ((long long)E + EPW - 1) / EPW;
        long long tcount = warps * 32;
        int blocks = (int)((tcount + 255) / 256);
        k_agg<<<blocks, 256>>>(src, gidx, sid, out, E);
    }
    // 3) scale by 1/count
    {
        int blocks = (nq + 255) / 256;
        k_fin<<<blocks, 256>>>((float4*)out, nq);
    }
}

// round 10
// speedup vs baseline: 1.5141x; 1.1645x over previous
#include <cuda_runtime.h>
#include <cuda_bf16.h>

#define FULL_MASK 0xffffffffu
#define EPW 128          // edges per warp-chunk (4 groups x 32 edges)
#define D   32           // feature dim (fixed by problem shape)

// Boundary tables: for every NON-EMPTY segment s, g_pos[s] = first edge index,
// g_end[s] = one-past-last edge index. Empty segments keep stale entries —
// deterministic (same inputs each replay, zero-initialized at load) and
// harmless (their sums are 0; inv stays finite). No reset needed.
__device__ int g_pos[1 << 20];   // supports N up to 1M
__device__ int g_end[1 << 20];

// ---------------------------------------------------------------------------
// Kernel 1: zero out + branch-free boundary marking on sorted sid.
// Thread i owns edge pairs (e, e+1) for e in [4i, 4i+3]. A boundary emits
// exactly two stores. Head: g_pos[sid[0]] = 0. Tail: g_end[sid[E-1]] = E.
// No loops, minimal divergence (~1/8 threads store anything).
// ---------------------------------------------------------------------------
__global__ void __launch_bounds__(256)
k_pre2(const int* __restrict__ sid,
       float4*    __restrict__ out4,
       int E, int nq)
{
    const int i = blockIdx.x * blockDim.x + threadIdx.x;

    if (i < nq) out4[i] = make_float4(0.f, 0.f, 0.f, 0.f);

    const int e0 = i * 4;
    if (e0 >= E) return;

    int a[5];
    if (e0 + 4 <= E) {
        int4 v = __ldg((const int4*)sid + i);
        a[0] = v.x; a[1] = v.y; a[2] = v.z; a[3] = v.w;
    } else {
        a[0] = __ldg(sid + e0);
        a[1] = (e0 + 1 < E) ? __ldg(sid + e0 + 1) : a[0];
        a[2] = (e0 + 2 < E) ? __ldg(sid + e0 + 2) : a[1];
        a[3] = (e0 + 3 < E) ? __ldg(sid + e0 + 3) : a[2];
    }
    a[4] = (e0 + 4 < E) ? __ldg(sid + e0 + 4) : a[3];

    if (i == 0) g_pos[a[0]] = 0;

    #pragma unroll
    for (int j = 0; j < 4; ++j) {
        const int e = e0 + j;
        if (e + 1 < E) {
            const int cur = a[j], ns = a[j + 1];
            if (ns != cur) { g_end[cur] = e + 1; g_pos[ns] = e + 1; }
        } else if (e + 1 == E) {
            g_end[a[j]] = E;
        }
    }
}

// ---------------------------------------------------------------------------
// 128-bit reduction (fire-and-forget) — sm_90+ vector atomic
// ---------------------------------------------------------------------------
__device__ __forceinline__ void red_add_v4(float4* p, float4 s) {
    asm volatile("red.global.add.v4.f32 [%0], {%1, %2, %3, %4};"
                 :: "l"(p), "f"(s.x), "f"(s.y), "f"(s.z), "f"(s.w)
                 : "memory");
}

__device__ __forceinline__ void flush_seg(float4* __restrict__ out4, int seg,
                                          float4 s, int sub) {
    red_add_v4(&out4[(long long)seg * 8 + sub], s);
}

// ---------------------------------------------------------------------------
// Kernel 2: gather + sorted-segment raw sum (round-3 engine, v4 flush).
// Warp = 4 groups of 8 lanes. Group g owns contiguous edges
// [start + g*32, start + g*32 + 32). Lane sub owns feature columns
// [sub*4, sub*4+4) as a float4. Phase 1 issues 8 independent LDG.128 row
// reads (MLP=8/lane); phase 2 run-length accumulates, flushing raw sums
// with ONE REDG.128 per lane on segment change. Nothing else inside.
// ---------------------------------------------------------------------------
__global__ void __launch_bounds__(256)
k_agg(const float* __restrict__ src,
      const int*   __restrict__ gidx,
      const int*   __restrict__ sid,
      float4*      __restrict__ out4,
      int E)
{
    const int lane = threadIdx.x & 31;
    const int sub  = lane & 7;
    const long long warp  = ((long long)blockIdx.x * blockDim.x + threadIdx.x) >> 5;
    const long long start = warp * (long long)EPW;
    if (start >= E) return;

    if (start + EPW <= E) {
        // ---------- fast path: full 128-edge chunk ----------
        int4 gi4 = __ldg((const int4*)(gidx + start) + lane);
        int4 si4 = __ldg((const int4*)(sid  + start) + lane);
        int gi[4] = {gi4.x, gi4.y, gi4.z, gi4.w};
        int si[4] = {si4.x, si4.y, si4.z, si4.w};

        int    cur = -1;
        float4 sum = make_float4(0.f, 0.f, 0.f, 0.f);

        #pragma unroll
        for (int jo = 0; jo < 32; jo += 8) {
            float4 val[8];
            #pragma unroll
            for (int jj = 0; jj < 8; ++jj) {
                const int j = jo + jj;
                int idx = __shfl_sync(FULL_MASK, gi[j & 3], j >> 2, 8);
                val[jj] = __ldg((const float4*)(src + (long long)idx * D) + sub);
            }
            #pragma unroll
            for (int jj = 0; jj < 8; ++jj) {
                const int j = jo + jj;
                int seg = __shfl_sync(FULL_MASK, si[j & 3], j >> 2, 8);
                if (seg != cur) {
                    if (cur >= 0) flush_seg(out4, cur, sum, sub);
                    cur = seg; sum = make_float4(0.f, 0.f, 0.f, 0.f);
                }
                sum.x += val[jj].x; sum.y += val[jj].y;
                sum.z += val[jj].z; sum.w += val[jj].w;
            }
        }
        flush_seg(out4, cur, sum, sub);
    } else {
        // ---------- tail path: partial chunk, per-group scalar loop ----------
        const int group = lane >> 3;
        long long gstart = start + (long long)group * 32;
        long long gend   = min(gstart + 32, (long long)E);

        int    cur = -1;
        float4 sum = make_float4(0.f, 0.f, 0.f, 0.f);

        for (long long e = gstart; e < gend; ++e) {
            int idx = __ldg(gidx + e);
            int seg = __ldg(sid  + e);
            float4 v = __ldg((const float4*)(src + (long long)idx * D) + sub);
            if (seg != cur) {
                if (cur >= 0) flush_seg(out4, cur, sum, sub);
                cur = seg; sum = make_float4(0.f, 0.f, 0.f, 0.f);
            }
            sum.x += v.x; sum.y += v.y; sum.z += v.z; sum.w += v.w;
        }
        if (cur >= 0) flush_seg(out4, cur, sum, sub);
    }
}

// ---------------------------------------------------------------------------
// Kernel 3: out[n][:] *= 1/max(g_end[n]-g_pos[n], 1)   (streaming, 26 MB)
// Stale entries for empty segments give a finite inv; sum is 0 -> out 0.
// ---------------------------------------------------------------------------
__global__ void k_fin(float4* __restrict__ out4, int nq) {
    int i = blockIdx.x * blockDim.x + threadIdx.x;
    if (i >= nq) return;
    const int n = i >> 3;
    const int s = __ldg(g_pos + n);
    const int t = __ldg(g_end + n);
    const float inv = 1.0f / (float)max(t - s, 1);
    float4 v = out4[i];
    v.x *= inv; v.y *= inv; v.z *= inv; v.w *= inv;
    out4[i] = v;
}

// ---------------------------------------------------------------------------
extern "C" void kernel_launch(void* const* d_in, const int* in_sizes, int n_in,
                              void* d_out, int out_size)
{
    const float* src  = (const float*)d_in[0];   // [N, 32] f32
    const int*   gidx = (const int*)  d_in[1];   // [E] i32
    const int*   sid  = (const int*)  d_in[2];   // [E] i32 (sorted)
    float4*      out4 = (float4*)d_out;          // [N, 32] f32

    const int E  = in_sizes[1];
    const int nq = out_size / 4;

    // 1) zero out + boundary marks
    {
        int threads_needed = (E + 3) / 4;
        if (threads_needed < nq) threads_needed = nq;
        int blocks = (threads_needed + 255) / 256;
        k_pre2<<<blocks, 256>>>(sid, out4, E, nq);
    }
    // 2) gather + raw segment sums (REDG.128 flush)
    {
        long long warps  = ((long long)E + EPW - 1) / EPW;
        long long tcount = warps * 32;
        int blocks = (int)((tcount + 255) / 256);
        k_agg<<<blocks, 256>>>(src, gidx, sid, out4, E);
    }
    // 3) scale by 1/count
    {
        int blocks = (nq + 255) / 256;
        k_fin<<<blocks, 256>>>(out4, nq);
    }
}